// round 16
// baseline (speedup 1.0000x reference)
#include <cuda_runtime.h>

// DynamicUpsamplingFilter: out[b,c,h,w] = sum_{dy,dx} x_pad[b,c,h+dy,w+dx] * filters[b,dy*3+dx,h,w]
// x: [4,128,180,320] f32, filters: [4,9,180,320] f32, out: [4,128,180,320] f32.
//
// R16 = R15 (best, 39.0us kernel: 4w x 2h tile, CCH=32, skewed pipeline,
// streaming stores) with the m (LDG.128) prefetch deepened to distance 3
// (quad buffer) and halo LDG.32s moved in-iteration (L1 hits on lines the
// vector loads fetched 3 iterations earlier — R12 proved this costs ~0).
// Freed halo buffers pay for the 4th m buffer: fv(72)+m(64)+halo(8)+misc
// ~160 regs, still launch_bounds(128,3) = 12 warps/SM, no spill.

constexpr int B = 4, C = 128, H = 180, W = 320;
constexpr int HW = H * W;
constexpr int WQ = W / 4;            // 80 pixel-quads per row
constexpr int HP = H / 2;            // 90 row-pairs
constexpr int CCH = 32;              // channels per thread
constexpr int NCQ = C / CCH;         // 4 channel-groups
constexpr int THREADS = 128;
constexpr int NTHREADS_TOTAL = B * NCQ * HP * WQ;  // 115200
constexpr int GRID = NTHREADS_TOTAL / THREADS;     // 900
constexpr int PFD = 3;               // m prefetch distance
constexpr int NBUF = 4;              // m buffers

__device__ __forceinline__ void stcs4(float* p, float a, float b, float c, float d)
{
    float4 v = make_float4(a, b, c, d);
    asm volatile("st.global.cs.v4.f32 [%0], {%1, %2, %3, %4};"
                 :: "l"(p), "f"(v.x), "f"(v.y), "f"(v.z), "f"(v.w) : "memory");
}

__global__ __launch_bounds__(THREADS, 3)
void duf_kernel(const float* __restrict__ x,
                const float* __restrict__ f,
                float* __restrict__ out)
{
    int idx = blockIdx.x * THREADS + threadIdx.x;

    // consecutive threads -> consecutive wq for coalescing
    int wq = idx % WQ;
    int t  = idx / WQ;
    int hp = t % HP;
    t /= HP;
    int cq = t % NCQ;
    int b  = t / NCQ;
    int w  = wq * 4;
    int h  = hp * 2;                 // output rows h, h+1

    // ---- filter taps for both output rows (pixels w..w+3) ----
    const float* fp0 = f + (size_t)b * 9 * HW + (size_t)h * W + w;
    float4 fv0[9], fv1[9];
#pragma unroll
    for (int i = 0; i < 9; ++i) {
        fv0[i] = *(const float4*)(fp0 + (size_t)i * HW);        // row h
        fv1[i] = *(const float4*)(fp0 + (size_t)i * HW + W);    // row h+1
    }

    // vertical boundaries
    if (hp == 0) {
#pragma unroll
        for (int i = 0; i < 3; ++i) fv0[i] = make_float4(0.f, 0.f, 0.f, 0.f);
    }
    if (hp == HP - 1) {
#pragma unroll
        for (int i = 6; i < 9; ++i) fv1[i] = make_float4(0.f, 0.f, 0.f, 0.f);
    }
    // horizontal boundaries
    if (w == 0) {
        fv0[0].x = 0.f; fv0[3].x = 0.f; fv0[6].x = 0.f;
        fv1[0].x = 0.f; fv1[3].x = 0.f; fv1[6].x = 0.f;
    }
    if (w == W - 4) {
        fv0[2].w = 0.f; fv0[5].w = 0.f; fv0[8].w = 0.f;
        fv1[2].w = 0.f; fv1[5].w = 0.f; fv1[8].w = 0.f;
    }

    // input rows h-1 .. h+2, clamped (dead loads in-bounds, filter zeroed)
    int roff[4];
    roff[0] = (hp > 0)      ? -W    : 0;     // row h-1
    roff[1] = 0;                              // row h
    roff[2] = W;                              // row h+1
    roff[3] = (hp < HP - 1) ? 2 * W : W;     // row h+2
    int offm1 = (w > 0)     ? -1 : 0;        // column w-1
    int offp4 = (w + 4 < W) ?  4 : 3;        // column w+4

    const float* xp = x   + ((size_t)b * C + cq * CCH) * HW + (size_t)h * W + w;
    float*       op = out + ((size_t)b * C + cq * CCH) * HW + (size_t)h * W + w;

    // ---- pipeline: m quad-buffered at distance 3; halos in-iteration ----
    float4 mb[NBUF][4];

    auto load_m = [&](float4 dst[4], int c) {
        const float* xc = xp + (size_t)c * HW;
#pragma unroll
        for (int r = 0; r < 4; ++r)
            dst[r] = *(const float4*)(xc + roff[r]);
    };

    // prologue: fill distance-3 pipe
#pragma unroll
    for (int p = 0; p < PFD; ++p)
        load_m(mb[p], p);

#pragma unroll
    for (int c = 0; c < CCH; ++c) {
        // prefetch m for c+PFD (consumed 3 iterations later)
        if (c + PFD < CCH) load_m(mb[(c + PFD) % NBUF], c + PFD);

        // halo loads for this channel: L1 hits (their lines were fetched by
        // this/neighbor threads' vector loads of channel c, 3 iterations ago)
        const float* xc = xp + (size_t)c * HW;
        float vm[4], vp[4];
#pragma unroll
        for (int r = 0; r < 4; ++r) {
            const float* row = xc + roff[r];
            vm[r] = __ldg(row + offm1);
            vp[r] = __ldg(row + offp4);
        }

        const float4* m = mb[c % NBUF];

        // output row h: input rows 0,1,2
        float a0 = 0.f, a1 = 0.f, a2 = 0.f, a3 = 0.f;
#pragma unroll
        for (int j = 0; j < 3; ++j) {
            float4 F0 = fv0[3 * j + 0], F1 = fv0[3 * j + 1], F2 = fv0[3 * j + 2];
            float4 mm = m[j]; float vml = vm[j], vpr = vp[j];
            a0 = fmaf(vml,  F0.x, a0); a0 = fmaf(mm.x, F1.x, a0); a0 = fmaf(mm.y, F2.x, a0);
            a1 = fmaf(mm.x, F0.y, a1); a1 = fmaf(mm.y, F1.y, a1); a1 = fmaf(mm.z, F2.y, a1);
            a2 = fmaf(mm.y, F0.z, a2); a2 = fmaf(mm.z, F1.z, a2); a2 = fmaf(mm.w, F2.z, a2);
            a3 = fmaf(mm.z, F0.w, a3); a3 = fmaf(mm.w, F1.w, a3); a3 = fmaf(vpr,  F2.w, a3);
        }
        // output row h+1: input rows 1,2,3
        float b0 = 0.f, b1 = 0.f, b2 = 0.f, b3 = 0.f;
#pragma unroll
        for (int j = 0; j < 3; ++j) {
            float4 F0 = fv1[3 * j + 0], F1 = fv1[3 * j + 1], F2 = fv1[3 * j + 2];
            float4 mm = m[j + 1]; float vml = vm[j + 1], vpr = vp[j + 1];
            b0 = fmaf(vml,  F0.x, b0); b0 = fmaf(mm.x, F1.x, b0); b0 = fmaf(mm.y, F2.x, b0);
            b1 = fmaf(mm.x, F0.y, b1); b1 = fmaf(mm.y, F1.y, b1); b1 = fmaf(mm.z, F2.y, b1);
            b2 = fmaf(mm.y, F0.z, b2); b2 = fmaf(mm.z, F1.z, b2); b2 = fmaf(mm.w, F2.z, b2);
            b3 = fmaf(mm.z, F0.w, b3); b3 = fmaf(mm.w, F1.w, b3); b3 = fmaf(vpr,  F2.w, b3);
        }

        float* oc = op + (size_t)c * HW;
        stcs4(oc,     a0, a1, a2, a3);
        stcs4(oc + W, b0, b1, b2, b3);
    }
}

extern "C" void kernel_launch(void* const* d_in, const int* in_sizes, int n_in,
                              void* d_out, int out_size)
{
    const float* x = (const float*)d_in[0];   // [4,128,180,320]
    const float* f = (const float*)d_in[1];   // [4,9,180,320]
    float* out = (float*)d_out;               // [4,128,180,320]

    duf_kernel<<<GRID, THREADS>>>(x, f, out);
}

// round 17
// speedup vs baseline: 1.0887x; 1.0887x over previous
#include <cuda_runtime.h>

// DynamicUpsamplingFilter: out[b,c,h,w] = sum_{dy,dx} x_pad[b,c,h+dy,w+dx] * filters[b,dy*3+dx,h,w]
// x: [4,128,180,320] f32, filters: [4,9,180,320] f32, out: [4,128,180,320] f32.
//
// R17 = R15 (best measured: 39.0us kernel / 45.8 total). 4w x 2h pixel
// tile, 32 channels/thread, register-resident filter bank (72 regs),
// skewed software pipeline (m LDG.128 triple-buffered at prefetch
// distance 2, halo LDG.32 double-buffered at distance 1), streaming
// st.global.cs stores. Only change vs R15: halo prefetch (consumed next
// iteration) issues BEFORE m prefetch (consumed in two) so the
// nearer-deadline loads get earlier LSU dispatch.
// Tested-and-rejected alternatives: shuffles (R3/R13: MIO critical path),
// smem filters (R14: crossbar serialization), occ>12 warps (R4/R11:
// spills / depth loss), m depth 3 (R12/R16: neutral-to-worse), 2-pixel
// tiles (R5), in-iteration halos at CCH=32 (R16).

constexpr int B = 4, C = 128, H = 180, W = 320;
constexpr int HW = H * W;
constexpr int WQ = W / 4;            // 80 pixel-quads per row
constexpr int HP = H / 2;            // 90 row-pairs
constexpr int CCH = 32;              // channels per thread
constexpr int NCQ = C / CCH;         // 4 channel-groups
constexpr int THREADS = 128;
constexpr int NTHREADS_TOTAL = B * NCQ * HP * WQ;  // 115200
constexpr int GRID = NTHREADS_TOTAL / THREADS;     // 900

__device__ __forceinline__ void stcs4(float* p, float a, float b, float c, float d)
{
    float4 v = make_float4(a, b, c, d);
    asm volatile("st.global.cs.v4.f32 [%0], {%1, %2, %3, %4};"
                 :: "l"(p), "f"(v.x), "f"(v.y), "f"(v.z), "f"(v.w) : "memory");
}

__global__ __launch_bounds__(THREADS, 3)
void duf_kernel(const float* __restrict__ x,
                const float* __restrict__ f,
                float* __restrict__ out)
{
    int idx = blockIdx.x * THREADS + threadIdx.x;

    // consecutive threads -> consecutive wq for coalescing
    int wq = idx % WQ;
    int t  = idx / WQ;
    int hp = t % HP;
    t /= HP;
    int cq = t % NCQ;
    int b  = t / NCQ;
    int w  = wq * 4;
    int h  = hp * 2;                 // output rows h, h+1

    // ---- filter taps for both output rows (pixels w..w+3) ----
    const float* fp0 = f + (size_t)b * 9 * HW + (size_t)h * W + w;
    float4 fv0[9], fv1[9];
#pragma unroll
    for (int i = 0; i < 9; ++i) {
        fv0[i] = *(const float4*)(fp0 + (size_t)i * HW);        // row h
        fv1[i] = *(const float4*)(fp0 + (size_t)i * HW + W);    // row h+1
    }

    // vertical boundaries
    if (hp == 0) {
#pragma unroll
        for (int i = 0; i < 3; ++i) fv0[i] = make_float4(0.f, 0.f, 0.f, 0.f);
    }
    if (hp == HP - 1) {
#pragma unroll
        for (int i = 6; i < 9; ++i) fv1[i] = make_float4(0.f, 0.f, 0.f, 0.f);
    }
    // horizontal boundaries
    if (w == 0) {
        fv0[0].x = 0.f; fv0[3].x = 0.f; fv0[6].x = 0.f;
        fv1[0].x = 0.f; fv1[3].x = 0.f; fv1[6].x = 0.f;
    }
    if (w == W - 4) {
        fv0[2].w = 0.f; fv0[5].w = 0.f; fv0[8].w = 0.f;
        fv1[2].w = 0.f; fv1[5].w = 0.f; fv1[8].w = 0.f;
    }

    // input rows h-1 .. h+2, clamped (dead loads in-bounds, filter zeroed)
    int roff[4];
    roff[0] = (hp > 0)      ? -W    : 0;     // row h-1
    roff[1] = 0;                              // row h
    roff[2] = W;                              // row h+1
    roff[3] = (hp < HP - 1) ? 2 * W : W;     // row h+2
    int offm1 = (w > 0)     ? -1 : 0;        // column w-1
    int offp4 = (w + 4 < W) ?  4 : 3;        // column w+4

    const float* xp = x   + ((size_t)b * C + cq * CCH) * HW + (size_t)h * W + w;
    float*       op = out + ((size_t)b * C + cq * CCH) * HW + (size_t)h * W + w;

    // ---- skewed software pipeline ----
    // m (LDG.128): triple buffer, prefetch distance 2
    // vm/vp (LDG.32): double buffer, prefetch distance 1
    float4 mb[3][4];
    float  vmb[2][4], vpb[2][4];

    auto load_m = [&](float4 dst[4], int c) {
        const float* xc = xp + (size_t)c * HW;
#pragma unroll
        for (int r = 0; r < 4; ++r)
            dst[r] = *(const float4*)(xc + roff[r]);
    };
    auto load_halo = [&](float dm[4], float dp[4], int c) {
        const float* xc = xp + (size_t)c * HW;
#pragma unroll
        for (int r = 0; r < 4; ++r) {
            const float* row = xc + roff[r];
            dm[r] = __ldg(row + offm1);
            dp[r] = __ldg(row + offp4);
        }
    };

    // prologue
    load_m(mb[0], 0);
    load_m(mb[1], 1);
    load_halo(vmb[0], vpb[0], 0);

#pragma unroll
    for (int c = 0; c < CCH; ++c) {
        // prefetches first (independent of this iteration's consumers);
        // halo (due next iteration) before m (due in two iterations)
        if (c + 1 < CCH) load_halo(vmb[(c + 1) % 2], vpb[(c + 1) % 2], c + 1);
        if (c + 2 < CCH) load_m(mb[(c + 2) % 3], c + 2);

        const float4* m  = mb[c % 3];
        const float*  vm = vmb[c % 2];
        const float*  vp = vpb[c % 2];

        // output row h: input rows 0,1,2
        float a0 = 0.f, a1 = 0.f, a2 = 0.f, a3 = 0.f;
#pragma unroll
        for (int j = 0; j < 3; ++j) {
            float4 F0 = fv0[3 * j + 0], F1 = fv0[3 * j + 1], F2 = fv0[3 * j + 2];
            float4 mm = m[j]; float vml = vm[j], vpr = vp[j];
            a0 = fmaf(vml,  F0.x, a0); a0 = fmaf(mm.x, F1.x, a0); a0 = fmaf(mm.y, F2.x, a0);
            a1 = fmaf(mm.x, F0.y, a1); a1 = fmaf(mm.y, F1.y, a1); a1 = fmaf(mm.z, F2.y, a1);
            a2 = fmaf(mm.y, F0.z, a2); a2 = fmaf(mm.z, F1.z, a2); a2 = fmaf(mm.w, F2.z, a2);
            a3 = fmaf(mm.z, F0.w, a3); a3 = fmaf(mm.w, F1.w, a3); a3 = fmaf(vpr,  F2.w, a3);
        }
        // output row h+1: input rows 1,2,3
        float b0 = 0.f, b1 = 0.f, b2 = 0.f, b3 = 0.f;
#pragma unroll
        for (int j = 0; j < 3; ++j) {
            float4 F0 = fv1[3 * j + 0], F1 = fv1[3 * j + 1], F2 = fv1[3 * j + 2];
            float4 mm = m[j + 1]; float vml = vm[j + 1], vpr = vp[j + 1];
            b0 = fmaf(vml,  F0.x, b0); b0 = fmaf(mm.x, F1.x, b0); b0 = fmaf(mm.y, F2.x, b0);
            b1 = fmaf(mm.x, F0.y, b1); b1 = fmaf(mm.y, F1.y, b1); b1 = fmaf(mm.z, F2.y, b1);
            b2 = fmaf(mm.y, F0.z, b2); b2 = fmaf(mm.z, F1.z, b2); b2 = fmaf(mm.w, F2.z, b2);
            b3 = fmaf(mm.z, F0.w, b3); b3 = fmaf(mm.w, F1.w, b3); b3 = fmaf(vpr,  F2.w, b3);
        }

        float* oc = op + (size_t)c * HW;
        stcs4(oc,     a0, a1, a2, a3);
        stcs4(oc + W, b0, b1, b2, b3);
    }
}

extern "C" void kernel_launch(void* const* d_in, const int* in_sizes, int n_in,
                              void* d_out, int out_size)
{
    const float* x = (const float*)d_in[0];   // [4,128,180,320]
    const float* f = (const float*)d_in[1];   // [4,9,180,320]
    float* out = (float*)d_out;               // [4,128,180,320]

    duf_kernel<<<GRID, THREADS>>>(x, f, out);
}